// round 2
// baseline (speedup 1.0000x reference)
#include <cuda_runtime.h>
#include <math.h>

#define N 512
#define D 512
#define SIGMA 0.5f
#define EPSV 1e-7f

// Scratch (static __device__ — no allocations allowed)
__device__ float g_F[N * N];      // F[i,j] = -sigma * ||f_i - f_j||, diag = 0
__device__ float g_norm[N];      // ||f_i||^2
__device__ float g_rowLoss[N];   // per-row partial of sum(pos_log_probs)

// ---------------------------------------------------------------------------
// Fixed-order block reduction (deterministic)
// ---------------------------------------------------------------------------
__device__ __forceinline__ float block_reduce_sum(float v, float* sh) {
    int t = threadIdx.x;
    #pragma unroll
    for (int o = 16; o > 0; o >>= 1)
        v += __shfl_down_sync(0xffffffffu, v, o);
    if ((t & 31) == 0) sh[t >> 5] = v;
    __syncthreads();
    if (t < 32) {
        int nw = blockDim.x >> 5;
        v = (t < nw) ? sh[t] : 0.f;
        #pragma unroll
        for (int o = 16; o > 0; o >>= 1)
            v += __shfl_down_sync(0xffffffffu, v, o);
        if (t == 0) sh[0] = v;
    }
    __syncthreads();
    float r = sh[0];
    __syncthreads();   // allow sh reuse by caller
    return r;
}

// ---------------------------------------------------------------------------
// K1: row squared norms
// ---------------------------------------------------------------------------
__global__ void __launch_bounds__(128) norm_kernel(const float* __restrict__ f) {
    __shared__ float red[32];
    int i = blockIdx.x;
    int t = threadIdx.x;
    const float4* row = (const float4*)(f + (size_t)i * D);
    float s = 0.f;
    #pragma unroll
    for (int c = t; c < D / 4; c += 128) {
        float4 v = row[c];
        s += v.x * v.x + v.y * v.y + v.z * v.z + v.w * v.w;
    }
    s = block_reduce_sum(s, red);
    if (t == 0) g_norm[i] = s;
}

// ---------------------------------------------------------------------------
// K2: Gram-based pairwise distance -> F.
// 32x32 output tile per CTA, 256 threads, 2x2 microtile per thread.
// ---------------------------------------------------------------------------
__global__ void __launch_bounds__(256) gram_kernel(const float* __restrict__ f) {
    __shared__ float As[32][33];
    __shared__ float Bs[32][33];
    int bi = blockIdx.y * 32;
    int bj = blockIdx.x * 32;
    int lt = threadIdx.x;
    int tx = lt & 15;
    int ty = lt >> 4;

    float acc00 = 0.f, acc01 = 0.f, acc10 = 0.f, acc11 = 0.f;

    for (int k0 = 0; k0 < D; k0 += 32) {
        #pragma unroll
        for (int q = 0; q < 4; q++) {
            int idx = lt + q * 256;       // 0..1023
            int r = idx >> 5, c = idx & 31;
            As[r][c] = f[(size_t)(bi + r) * D + k0 + c];
            Bs[r][c] = f[(size_t)(bj + r) * D + k0 + c];
        }
        __syncthreads();
        #pragma unroll
        for (int k = 0; k < 32; k++) {
            float a0 = As[2 * ty][k];
            float a1 = As[2 * ty + 1][k];
            float b0 = Bs[2 * tx][k];
            float b1 = Bs[2 * tx + 1][k];
            acc00 += a0 * b0;
            acc01 += a0 * b1;
            acc10 += a1 * b0;
            acc11 += a1 * b1;
        }
        __syncthreads();
    }

    float accs[2][2] = {{acc00, acc01}, {acc10, acc11}};
    #pragma unroll
    for (int u = 0; u < 2; u++) {
        #pragma unroll
        for (int v = 0; v < 2; v++) {
            int i = bi + 2 * ty + u;
            int j = bj + 2 * tx + v;
            float sq = g_norm[i] + g_norm[j] - 2.f * accs[u][v];
            float F = (i == j) ? 0.f : (-SIGMA * sqrtf(fmaxf(sq, 0.f)));
            g_F[(size_t)i * N + j] = F;
        }
    }
}

// ---------------------------------------------------------------------------
// K3: per-row softmax + denom (O(n^2) per row) + partial loss.
// One CTA (512 threads) per row i. Thread t owns column k=t.
// denom[i,k] = sum_{j != i} S[i,j] * (R[i,j] >= R[i,k])
// rowLoss[i] = sum_k F[i,k] - sum_{k != i} log(denom[i,k] + eps)
// ---------------------------------------------------------------------------
__global__ void __launch_bounds__(512) row_kernel(const float* __restrict__ label) {
    __shared__ __align__(16) float2 rs[N];   // (R, S) pairs, S zeroed at j==i
    __shared__ float red[32];

    int i = blockIdx.x;
    int t = threadIdx.x;

    float li = label[i];
    float Ft = g_F[(size_t)i * N + t];       // F[i,t]; row max is exactly 0 (diag)
    float e = expf(Ft);                       // softmax numerator (max already 0)

    float rowsum = block_reduce_sum(e, red);
    float inv = 1.f / rowsum;

    float Rt = fabsf(li - label[t]);
    rs[t] = make_float2(Rt, (t == i) ? 0.f : e * inv);
    __syncthreads();

    // Vectorized broadcast scan over the row: 2 (R,S) pairs per LDS.128
    const float4* rs4 = (const float4*)rs;
    float d0 = 0.f, d1 = 0.f;
    #pragma unroll 8
    for (int j = 0; j < N / 2; j++) {
        float4 v = rs4[j];
        if (v.x >= Rt) d0 += v.y;
        if (v.z >= Rt) d1 += v.w;
    }
    float denom = d0 + d1;

    float partial = Ft;
    if (t != i) partial -= logf(denom + EPSV);

    float rl = block_reduce_sum(partial, red);
    if (t == 0) g_rowLoss[i] = rl;
}

// ---------------------------------------------------------------------------
// K4: final reduce -> loss scalar
// ---------------------------------------------------------------------------
__global__ void __launch_bounds__(512) final_kernel(float* __restrict__ out) {
    __shared__ float red[32];
    float v = g_rowLoss[threadIdx.x];
    float s = block_reduce_sum(v, red);
    if (threadIdx.x == 0)
        out[0] = -s / (float)(N * (N - 1));
}

// ---------------------------------------------------------------------------
extern "C" void kernel_launch(void* const* d_in, const int* in_sizes, int n_in,
                              void* d_out, int out_size) {
    const float* feature = (const float*)d_in[0];   // [512, 512] fp32
    const float* label   = (const float*)d_in[1];   // [512, 1]  fp32
    float* out = (float*)d_out;

    norm_kernel<<<N, 128>>>(feature);
    gram_kernel<<<dim3(16, 16), 256>>>(feature);
    row_kernel<<<N, 512>>>(label);
    final_kernel<<<1, 512>>>(out);
}